// round 5
// baseline (speedup 1.0000x reference)
#include <cuda_runtime.h>
#include <cstdint>

// Packed fp32x2 FMA (sm_100+): 2 fp32 FMAs per instruction, only reachable via PTX.
#define FMA2(d, a, b, c) \
    asm("fma.rn.f32x2 %0, %1, %2, %3;" : "=l"(d) : "l"(a), "l"(b), "l"(c))

__device__ __forceinline__ unsigned long long pack2(float lo, float hi) {
    unsigned long long r;
    asm("mov.b64 %0, {%1, %2};" : "=l"(r) : "f"(lo), "f"(hi));
    return r;
}
__device__ __forceinline__ void unpack2(unsigned long long v, float& lo, float& hi) {
    asm("mov.b64 {%0, %1}, %2;" : "=f"(lo), "=f"(hi) : "l"(v));
}

// Streaming store: write-once output, evict-first in L2.
__device__ __forceinline__ void stcs128(float* p, float a, float b, float c, float d) {
    asm volatile("st.global.cs.v4.f32 [%0], {%1, %2, %3, %4};"
                 :: "l"(p), "f"(a), "f"(b), "f"(c), "f"(d) : "memory");
}

constexpr int H = 256, W = 256, F = 64, BATCH = 32;
constexpr int HW = H * W;
constexpr int TX = 32, TY = 4;          // 128 threads per block
constexpr int PX = 4,  PY = 4;          // 4x4 output pixels per thread
constexpr int TILE_X = TX * PX;         // 128
constexpr int TILE_Y = TY * PY;         // 16

// minBlocks=7 caps ptxas at 72 regs -> 7 CTAs/SM -> all 1024 blocks resident
// in ONE wave (148*7 = 1036 >= 1024). At 82 regs we had a 136-block tail wave.
__global__ __launch_bounds__(TX * TY, 7)
void spiking_conv_kernel(const float* __restrict__ tj,
                         const float* __restrict__ kw,
                         const float* __restrict__ Bb,
                         const float* __restrict__ Di,
                         float* __restrict__ out)
{
    // Weights packed (w,w) once per block; bias folded: c = 1 - D_i[0,f] - B[f]
    __shared__ unsigned long long w2[F][9];
    __shared__ unsigned long long b2[F];

    const int tid = threadIdx.y * TX + threadIdx.x;
    for (int i = tid; i < F * 9; i += TX * TY) {
        float w = kw[i];
        w2[i / 9][i % 9] = pack2(w, w);
    }
    for (int i = tid; i < F; i += TX * TY) {
        float c = 1.0f - Di[i] - Bb[i];   // D_i row 0; B is (64,1) contiguous
        b2[i] = pack2(c, c);
    }
    __syncthreads();

    const int b  = blockIdx.z;
    const int x0 = blockIdx.x * TILE_X + threadIdx.x * PX;
    const int y0 = blockIdx.y * TILE_Y + threadIdx.y * PY;
    const float* __restrict__ inp = tj + (size_t)b * HW;

    // Load the 6x6 input patch (rows y0-1..y0+4, cols x0-1..x0+4) with zero
    // padding, packing horizontal pairs on the fly:
    //   p[r][j] = (in[r][j], in[r][j+1]); pixel pair (x0,x0+1) uses p[.][dx],
    //   pair (x0+2,x0+3) uses p[.][dx+2].
    unsigned long long p[6][5];
    #pragma unroll
    for (int r = 0; r < 6; r++) {
        const int iy = y0 - 1 + r;
        const bool yok = (iy >= 0) & (iy < H);
        float row[6];
        #pragma unroll
        for (int c = 0; c < 6; c++) {
            const int ix = x0 - 1 + c;
            const bool ok = yok & (ix >= 0) & (ix < W);
            row[c] = ok ? __ldg(inp + iy * W + ix) : 0.0f;
        }
        #pragma unroll
        for (int j = 0; j < 5; j++)
            p[r][j] = pack2(row[j], row[j + 1]);
    }

    // Incremental output pointer: avoids a 64-bit IMAD per filter.
    float* __restrict__ of = out + (size_t)b * F * HW + (size_t)y0 * W + x0;

    #pragma unroll 1
    for (int f = 0; f < F; f++, of += HW) {
        unsigned long long wf[9];
        #pragma unroll
        for (int t = 0; t < 9; t++) wf[t] = w2[f][t];
        const unsigned long long bias = b2[f];

        #pragma unroll
        for (int r = 0; r < PY; r++) {
            unsigned long long a01 = bias, a23 = bias;
            #pragma unroll
            for (int k = 0; k < 3; k++) {
                #pragma unroll
                for (int dx = 0; dx < 3; dx++) {
                    FMA2(a01, wf[3 * k + dx], p[r + k][dx],     a01);
                    FMA2(a23, wf[3 * k + dx], p[r + k][dx + 2], a23);
                }
            }
            float v0, v1, v2, v3;
            unpack2(a01, v0, v1);
            unpack2(a23, v2, v3);
            stcs128(of + r * W,
                    fminf(v0, 1.0f), fminf(v1, 1.0f),
                    fminf(v2, 1.0f), fminf(v3, 1.0f));
        }
    }
}

extern "C" void kernel_launch(void* const* d_in, const int* in_sizes, int n_in,
                              void* d_out, int out_size)
{
    const float* tj = (const float*)d_in[0];   // (32,1,256,256)
    const float* kw = (const float*)d_in[1];   // (64,1,3,3)
    const float* Bb = (const float*)d_in[2];   // (64,1)
    const float* Di = (const float*)d_in[3];   // (9,64) — row 0 used
    float* out = (float*)d_out;                // (32,64,256,256)

    dim3 block(TX, TY, 1);
    dim3 grid(W / TILE_X, H / TILE_Y, BATCH);  // (2, 16, 32) = 1024 blocks
    spiking_conv_kernel<<<grid, block>>>(tj, kw, Bb, Di, out);
}

// round 6
// speedup vs baseline: 1.1372x; 1.1372x over previous
#include <cuda_runtime.h>
#include <cstdint>

// Packed fp32x2 FMA (sm_100+): 2 fp32 FMAs per instruction, only reachable via PTX.
#define FMA2(d, a, b, c) \
    asm("fma.rn.f32x2 %0, %1, %2, %3;" : "=l"(d) : "l"(a), "l"(b), "l"(c))

__device__ __forceinline__ unsigned long long pack2(float lo, float hi) {
    unsigned long long r;
    asm("mov.b64 %0, {%1, %2};" : "=l"(r) : "f"(lo), "f"(hi));
    return r;
}
__device__ __forceinline__ void unpack2(unsigned long long v, float& lo, float& hi) {
    asm("mov.b64 {%0, %1}, %2;" : "=f"(lo), "=f"(hi) : "l"(v));
}

// Streaming store: write-once output, evict-first in L2.
__device__ __forceinline__ void stcs128(float* p, float a, float b, float c, float d) {
    asm volatile("st.global.cs.v4.f32 [%0], {%1, %2, %3, %4};"
                 :: "l"(p), "f"(a), "f"(b), "f"(c), "f"(d) : "memory");
}

constexpr int H = 256, W = 256, F = 64, BATCH = 32;
constexpr int HW = H * W;
constexpr int TX = 32, TY = 4;          // 128 threads per block
constexpr int PX = 4,  PY = 2;          // 4x2 output pixels per thread
constexpr int TILE_X = TX * PX;         // 128
constexpr int TILE_Y = TY * PY;         // 8

// PY=2 shrinks the live patch to p[4][5] (40 regs), so natural usage ~62 regs.
// The 8-CTA bound (64-reg ceiling) is a gentle cap, NOT a squeeze (R5 lesson:
// capping 12% below natural usage caused remat/spill and a regression).
// 8 CTAs/SM -> 1184 resident blocks vs grid 2048 -> finish ratio 1.73 half-
// tiles ~= 0.87x of the old 1.15-wave schedule, plus deeper store MLP.
__global__ __launch_bounds__(TX * TY, 8)
void spiking_conv_kernel(const float* __restrict__ tj,
                         const float* __restrict__ kw,
                         const float* __restrict__ Bb,
                         const float* __restrict__ Di,
                         float* __restrict__ out)
{
    // Weights packed (w,w) once per block; bias folded: c = 1 - D_i[0,f] - B[f]
    __shared__ unsigned long long w2[F][9];
    __shared__ unsigned long long b2[F];

    const int tid = threadIdx.y * TX + threadIdx.x;
    for (int i = tid; i < F * 9; i += TX * TY) {
        float w = kw[i];
        w2[i / 9][i % 9] = pack2(w, w);
    }
    for (int i = tid; i < F; i += TX * TY) {
        float c = 1.0f - Di[i] - Bb[i];   // D_i row 0; B is (64,1) contiguous
        b2[i] = pack2(c, c);
    }
    __syncthreads();

    const int b  = blockIdx.z;
    const int x0 = blockIdx.x * TILE_X + threadIdx.x * PX;
    const int y0 = blockIdx.y * TILE_Y + threadIdx.y * PY;
    const float* __restrict__ inp = tj + (size_t)b * HW;

    // Load the (PY+2)x6 input patch (rows y0-1..y0+PY, cols x0-1..x0+4) with
    // zero padding, packing horizontal pairs on the fly:
    //   p[r][j] = (in[r][j], in[r][j+1]); pixel pair (x0,x0+1) uses p[.][dx],
    //   pair (x0+2,x0+3) uses p[.][dx+2].
    unsigned long long p[PY + 2][5];
    #pragma unroll
    for (int r = 0; r < PY + 2; r++) {
        const int iy = y0 - 1 + r;
        const bool yok = (iy >= 0) & (iy < H);
        float row[6];
        #pragma unroll
        for (int c = 0; c < 6; c++) {
            const int ix = x0 - 1 + c;
            const bool ok = yok & (ix >= 0) & (ix < W);
            row[c] = ok ? __ldg(inp + iy * W + ix) : 0.0f;
        }
        #pragma unroll
        for (int j = 0; j < 5; j++)
            p[r][j] = pack2(row[j], row[j + 1]);
    }

    // Incremental output pointer: avoids a 64-bit IMAD per filter.
    float* __restrict__ of = out + (size_t)b * F * HW + (size_t)y0 * W + x0;

    #pragma unroll 1
    for (int f = 0; f < F; f++, of += HW) {
        unsigned long long wf[9];
        #pragma unroll
        for (int t = 0; t < 9; t++) wf[t] = w2[f][t];
        const unsigned long long bias = b2[f];

        #pragma unroll
        for (int r = 0; r < PY; r++) {
            unsigned long long a01 = bias, a23 = bias;
            #pragma unroll
            for (int k = 0; k < 3; k++) {
                #pragma unroll
                for (int dx = 0; dx < 3; dx++) {
                    FMA2(a01, wf[3 * k + dx], p[r + k][dx],     a01);
                    FMA2(a23, wf[3 * k + dx], p[r + k][dx + 2], a23);
                }
            }
            float v0, v1, v2, v3;
            unpack2(a01, v0, v1);
            unpack2(a23, v2, v3);
            stcs128(of + r * W,
                    fminf(v0, 1.0f), fminf(v1, 1.0f),
                    fminf(v2, 1.0f), fminf(v3, 1.0f));
        }
    }
}

extern "C" void kernel_launch(void* const* d_in, const int* in_sizes, int n_in,
                              void* d_out, int out_size)
{
    const float* tj = (const float*)d_in[0];   // (32,1,256,256)
    const float* kw = (const float*)d_in[1];   // (64,1,3,3)
    const float* Bb = (const float*)d_in[2];   // (64,1)
    const float* Di = (const float*)d_in[3];   // (9,64) — row 0 used
    float* out = (float*)d_out;                // (32,64,256,256)

    dim3 block(TX, TY, 1);
    dim3 grid(W / TILE_X, H / TILE_Y, BATCH);  // (2, 32, 32) = 2048 blocks
    spiking_conv_kernel<<<grid, block>>>(tj, kw, Bb, Di, out);
}